// round 3
// baseline (speedup 1.0000x reference)
#include <cuda_runtime.h>

// Problem constants (fixed by the dataset)
#define BATCH   128
#define IN_DIM  2048
#define HID     2048
#define OUT_DIM 512
#define TSTEPS  32
#define VDECAY  0.5f
#define VTH     0.5f

// Split-K chunk size hypothesis: reference GEMM = 4 contiguous chunks of 512,
// serial in-order FMA within chunk, chunk sums combined left-associatively.
#define KCHUNK  512

// ---------------- device scratch (no allocations allowed) ----------------
__device__ float g_xt[TSTEPS * BATCH * IN_DIM];   // transposed input spikes [T,B,K]
__device__ float g_v0[BATCH * HID];
__device__ float g_s0[BATCH * HID];
__device__ float g_v1[BATCH * HID];
__device__ float g_s1[BATCH * HID];
__device__ float g_vo[BATCH * OUT_DIM];
__device__ float g_so[BATCH * OUT_DIM];

// ---------------- setup: copy initial state, zero output ----------------
__global__ void setup_kernel(const float* __restrict__ h0v, const float* __restrict__ h0s,
                             const float* __restrict__ h1v, const float* __restrict__ h1s,
                             const float* __restrict__ ov,  const float* __restrict__ os,
                             float* __restrict__ out) {
    int i = blockIdx.x * blockDim.x + threadIdx.x;
    int stride = gridDim.x * blockDim.x;
    for (int idx = i; idx < BATCH * HID; idx += stride) {
        g_v0[idx] = h0v[idx];
        g_s0[idx] = h0s[idx];
        g_v1[idx] = h1v[idx];
        g_s1[idx] = h1s[idx];
    }
    for (int idx = i; idx < BATCH * OUT_DIM; idx += stride) {
        g_vo[idx] = ov[idx];
        g_so[idx] = os[idx];
        out[idx]  = 0.0f;
    }
}

// ---------------- transpose spike_data [B, K, T] -> [T, B, K] ----------------
__global__ void transpose_kernel(const float* __restrict__ sd) {
    __shared__ float tile[32][33];
    int b  = blockIdx.y;
    int k0 = blockIdx.x * 32;
    int tx = threadIdx.x;  // 0..31
    int ty = threadIdx.y;  // 0..7
#pragma unroll
    for (int i = 0; i < 4; i++) {
        int kl = ty + i * 8;
        tile[kl][tx] = sd[(b * IN_DIM + k0 + kl) * TSTEPS + tx];  // coalesced over tx (=t)
    }
    __syncthreads();
#pragma unroll
    for (int i = 0; i < 4; i++) {
        int t = ty + i * 8;
        g_xt[(t * BATCH + b) * IN_DIM + k0 + tx] = tile[tx][t];   // coalesced over tx (=k)
    }
}

// ---------------- fused GEMM + LIF update (split-K rounding replica) ----------------
// C[b][n] = sum over 4 chunks; each chunk: serial in-order FFMA over 512 k's.
// Chunks combined left-associatively with plain fp32 adds.
// Then LIF: v = (decay + C) + bias ; s = (v > VTH). decay term is rounding-exact.
// Tiles: BM=32 (batch), BN=64 (neurons), BK=16, 256 threads, thread tile 2x4.
template <int N, int K, bool ACC_OUT>
__global__ __launch_bounds__(256) void lif_gemm_kernel(
    const float* __restrict__ X,      // [BATCH, K]
    const float* __restrict__ W,      // [N, K]
    const float* __restrict__ bias,   // [N]
    float* __restrict__ v,            // [BATCH, N] in/out
    float* __restrict__ s,            // [BATCH, N] in/out (prev spike -> new spike)
    float* __restrict__ out)          // [BATCH, N] accumulator (only if ACC_OUT)
{
    const int BM = 32, BN = 64, BK = 16;
    __shared__ float Xs[BK][34];   // padded: conflict-free STS, 8B-aligned float2 LDS
    __shared__ float Ws[BK][68];   // padded: 16B-aligned float4 LDS

    const int tid = threadIdx.x;          // 0..255
    const int m0 = blockIdx.y * BM;
    const int n0 = blockIdx.x * BN;

    const int rowg = tid >> 4;            // 0..15 -> rows rowg*2 + {0,1}
    const int colg = tid & 15;            // 0..15 -> cols colg*4 + {0..3}

    const int lk = tid & 15;              // k index for loads
    const int lr = tid >> 4;              // 0..15 row/col group for loads

    float tot[2][4];   // left-assoc sum of chunk results
    float acc[2][4];   // current chunk accumulator (serial in-order FFMA)
#pragma unroll
    for (int i = 0; i < 2; i++)
#pragma unroll
        for (int j = 0; j < 4; j++) { tot[i][j] = 0.0f; acc[i][j] = 0.0f; }

    const float* Xrow0 = X + (m0 + lr) * K + lk;
    const float* Xrow1 = X + (m0 + lr + 16) * K + lk;

    for (int c0 = 0; c0 < K; c0 += KCHUNK) {
        for (int k0 = c0; k0 < c0 + KCHUNK; k0 += BK) {
            // X tile [BM x BK] -> Xs[k][m] (transposed in smem)
            Xs[lk][lr]      = Xrow0[k0];
            Xs[lk][lr + 16] = Xrow1[k0];
            // W tile [BN x BK] -> Ws[k][n]
#pragma unroll
            for (int u = 0; u < 4; u++) {
                int n = lr + u * 16;
                Ws[lk][n] = W[(n0 + n) * K + k0 + lk];
            }
            __syncthreads();

#pragma unroll
            for (int kk = 0; kk < BK; kk++) {
                float2 a = *reinterpret_cast<const float2*>(&Xs[kk][rowg * 2]);
                float4 bb = *reinterpret_cast<const float4*>(&Ws[kk][colg * 4]);
                // serial in-order FFMA per output element
                acc[0][0] = __fmaf_rn(a.x, bb.x, acc[0][0]);
                acc[0][1] = __fmaf_rn(a.x, bb.y, acc[0][1]);
                acc[0][2] = __fmaf_rn(a.x, bb.z, acc[0][2]);
                acc[0][3] = __fmaf_rn(a.x, bb.w, acc[0][3]);
                acc[1][0] = __fmaf_rn(a.y, bb.x, acc[1][0]);
                acc[1][1] = __fmaf_rn(a.y, bb.y, acc[1][1]);
                acc[1][2] = __fmaf_rn(a.y, bb.z, acc[1][2]);
                acc[1][3] = __fmaf_rn(a.y, bb.w, acc[1][3]);
            }
            __syncthreads();
        }
        // fold chunk into running total (left-associative), reset chunk acc
#pragma unroll
        for (int i = 0; i < 2; i++)
#pragma unroll
            for (int j = 0; j < 4; j++) {
                tot[i][j] = __fadd_rn(tot[i][j], acc[i][j]);
                acc[i][j] = 0.0f;
            }
    }

    // epilogue: LIF update (decay term is rounding-exact: 0.5*v exact, (1-s) in {0,1})
#pragma unroll
    for (int i = 0; i < 2; i++) {
        int b = m0 + rowg * 2 + i;
#pragma unroll
        for (int j = 0; j < 4; j++) {
            int n = n0 + colg * 4 + j;
            int idx = b * N + n;
            float decay = __fmul_rn(__fmul_rn(VDECAY, v[idx]), __fadd_rn(1.0f, -s[idx]));
            float vv = __fadd_rn(__fadd_rn(decay, tot[i][j]), bias[n]);
            float ss = (vv > VTH) ? 1.0f : 0.0f;
            v[idx] = vv;
            s[idx] = ss;
            if (ACC_OUT) out[idx] += ss;
        }
    }
}

// ---------------- launcher ----------------
extern "C" void kernel_launch(void* const* d_in, const int* in_sizes, int n_in,
                              void* d_out, int out_size) {
    (void)in_sizes; (void)n_in; (void)out_size;
    const float* sd  = (const float*)d_in[0];
    const float* h0v = (const float*)d_in[1];
    const float* h0s = (const float*)d_in[2];
    const float* h1v = (const float*)d_in[3];
    const float* h1s = (const float*)d_in[4];
    const float* ov  = (const float*)d_in[5];
    const float* os  = (const float*)d_in[6];
    const float* W0  = (const float*)d_in[7];
    const float* b0  = (const float*)d_in[8];
    const float* W1  = (const float*)d_in[9];
    const float* b1  = (const float*)d_in[10];
    const float* Wo  = (const float*)d_in[11];
    const float* bo  = (const float*)d_in[12];
    float* out = (float*)d_out;

    float *xt, *v0, *s0, *v1, *s1, *vo, *so;
    cudaGetSymbolAddress((void**)&xt, g_xt);
    cudaGetSymbolAddress((void**)&v0, g_v0);
    cudaGetSymbolAddress((void**)&s0, g_s0);
    cudaGetSymbolAddress((void**)&v1, g_v1);
    cudaGetSymbolAddress((void**)&s1, g_s1);
    cudaGetSymbolAddress((void**)&vo, g_vo);
    cudaGetSymbolAddress((void**)&so, g_so);

    setup_kernel<<<1024, 256>>>(h0v, h0s, h1v, h1s, ov, os, out);

    dim3 tb(32, 8);
    dim3 tg(IN_DIM / 32, BATCH);
    transpose_kernel<<<tg, tb>>>(sd);

    dim3 gridH(HID / 64, BATCH / 32);      // (32, 4) = 128 CTAs
    dim3 gridO(OUT_DIM / 64, BATCH / 32);  // (8, 4)  = 32 CTAs

    for (int t = 0; t < TSTEPS; t++) {
        lif_gemm_kernel<HID, IN_DIM, false><<<gridH, 256>>>(
            xt + (size_t)t * BATCH * IN_DIM, W0, b0, v0, s0, nullptr);
        lif_gemm_kernel<HID, HID, false><<<gridH, 256>>>(
            s0, W1, b1, v1, s1, nullptr);
        lif_gemm_kernel<OUT_DIM, HID, true><<<gridO, 256>>>(
            s1, Wo, bo, vo, so, out);
    }
}

// round 4
// speedup vs baseline: 1.7834x; 1.7834x over previous
#include <cuda_runtime.h>

// Problem constants (fixed by the dataset)
#define BATCH   128
#define IN_DIM  2048
#define HID     2048
#define OUT_DIM 512
#define TSTEPS  32
#define VDECAY  0.5f
#define VTH     0.5f
#define KCHUNK  512   // reference split-K chunk (verified bit-exact in R2)

// ---------------- device scratch (no allocations allowed) ----------------
__device__ float g_xt[TSTEPS * BATCH * IN_DIM];     // [T*B, K] transposed input
__device__ float g_g0[TSTEPS * BATCH * HID];        // layer0 raw GEMM results [T*B, H]
__device__ float g_s0all[TSTEPS * BATCH * HID];     // layer0 spikes per t [T*B, H]
__device__ float g_v1[BATCH * HID];
__device__ float g_s1[BATCH * HID];
__device__ float g_vo[BATCH * OUT_DIM];
__device__ float g_so[BATCH * OUT_DIM];

// ---------------- setup: copy initial state, zero output ----------------
__global__ void setup_kernel(const float* __restrict__ h1v, const float* __restrict__ h1s,
                             const float* __restrict__ ov,  const float* __restrict__ os,
                             float* __restrict__ out) {
    int i = blockIdx.x * blockDim.x + threadIdx.x;
    int stride = gridDim.x * blockDim.x;
    for (int idx = i; idx < BATCH * HID; idx += stride) {
        g_v1[idx] = h1v[idx];
        g_s1[idx] = h1s[idx];
    }
    for (int idx = i; idx < BATCH * OUT_DIM; idx += stride) {
        g_vo[idx] = ov[idx];
        g_so[idx] = os[idx];
        out[idx]  = 0.0f;
    }
}

// ---------------- transpose spike_data [B, K, T] -> [T, B, K] ----------------
__global__ void transpose_kernel(const float* __restrict__ sd) {
    __shared__ float tile[32][33];
    int b  = blockIdx.y;
    int k0 = blockIdx.x * 32;
    int tx = threadIdx.x;  // 0..31
    int ty = threadIdx.y;  // 0..7
#pragma unroll
    for (int i = 0; i < 4; i++) {
        int kl = ty + i * 8;
        tile[kl][tx] = sd[(b * IN_DIM + k0 + kl) * TSTEPS + tx];
    }
    __syncthreads();
#pragma unroll
    for (int i = 0; i < 4; i++) {
        int t = ty + i * 8;
        g_xt[(t * BATCH + b) * IN_DIM + k0 + tx] = tile[tx][t];
    }
}

// ---------------- layer0 LIF scan over time (elementwise) ----------------
// v = (0.5*v*(1-s) + gemm) + bias ; s = (v > VTH). Same rounding as GEMM epilogue.
__global__ void lif0_scan_kernel(const float* __restrict__ h0v, const float* __restrict__ h0s,
                                 const float* __restrict__ b0) {
    int idx = blockIdx.x * blockDim.x + threadIdx.x;
    if (idx >= BATCH * HID) return;
    int h = idx % HID;
    float vv = h0v[idx];
    float ss = h0s[idx];
    float bb = b0[h];
#pragma unroll
    for (int t = 0; t < TSTEPS; t++) {
        float g = g_g0[t * BATCH * HID + idx];
        float decay = __fmul_rn(__fmul_rn(VDECAY, vv), __fadd_rn(1.0f, -ss));
        vv = __fadd_rn(__fadd_rn(decay, g), bb);
        ss = (vv > VTH) ? 1.0f : 0.0f;
        g_s0all[t * BATCH * HID + idx] = ss;
    }
}

// ---------------- double-buffered GEMM (+ optional fused LIF) ----------------
// C[m][n] = sum_k X[m][k]*W[n][k], per-element rounding = 4 serial chunks of 512,
// folded left-associatively (bit-exact contract from R2).
// EPI: 0 = LIF update (v,s) ; 1 = LIF + out accumulation ; 2 = raw store to out.
template <int N, int K, int BM, int BN, int TM, int TN, int THREADS, int EPI>
__global__ __launch_bounds__(THREADS) void lif_gemm_kernel(
    const float* __restrict__ X,
    const float* __restrict__ W,
    const float* __restrict__ bias,
    float* __restrict__ v,
    float* __restrict__ s,
    float* __restrict__ out)
{
    constexpr int BK  = 16;
    constexpr int NT  = K / BK;            // number of k-tiles
    constexpr int CH  = KCHUNK / BK;       // tiles per rounding chunk (32)
    constexpr int XP  = 2;                 // Xs pad (float2-friendly)
    constexpr int WP  = (TN == 4) ? 4 : 2; // Ws pad (float4/float2-friendly)
    constexpr int XLD = BM * BK / THREADS; // X elems per thread per tile
    constexpr int WLD = BN * BK / THREADS; // W elems per thread per tile
    constexpr int RS  = THREADS / BK;      // row stride for loads

    __shared__ __align__(16) float Xs[2][BK][BM + XP];
    __shared__ __align__(16) float Ws[2][BK][BN + WP];

    const int tid = threadIdx.x;
    const int m0 = blockIdx.y * BM;
    const int n0 = blockIdx.x * BN;

    const int lk = tid % BK;
    const int lr = tid / BK;
    const float* Xp = X + (size_t)(m0 + lr) * K + lk;
    const float* Wp = W + (size_t)(n0 + lr) * K + lk;

    const int tx = tid % (BN / TN);
    const int ty = tid / (BN / TN);

    float xr[XLD], wr[WLD];
    float acc[TM][TN], tot[TM][TN];
#pragma unroll
    for (int i = 0; i < TM; i++)
#pragma unroll
        for (int j = 0; j < TN; j++) { acc[i][j] = 0.0f; tot[i][j] = 0.0f; }

    // prologue: tile0 -> regs -> buf0 ; tile1 -> regs (in flight)
#pragma unroll
    for (int i = 0; i < XLD; i++) xr[i] = Xp[i * RS * K];
#pragma unroll
    for (int i = 0; i < WLD; i++) wr[i] = Wp[i * RS * K];
#pragma unroll
    for (int i = 0; i < XLD; i++) Xs[0][lk][lr + i * RS] = xr[i];
#pragma unroll
    for (int i = 0; i < WLD; i++) Ws[0][lk][lr + i * RS] = wr[i];
#pragma unroll
    for (int i = 0; i < XLD; i++) xr[i] = Xp[i * RS * K + BK];
#pragma unroll
    for (int i = 0; i < WLD; i++) wr[i] = Wp[i * RS * K + BK];
    __syncthreads();

    for (int t = 0; t < NT; t++) {
        const int cur = t & 1;
        if (t + 1 < NT) {
            // stage tile t+1 into the other buffer (read in next iteration)
#pragma unroll
            for (int i = 0; i < XLD; i++) Xs[cur ^ 1][lk][lr + i * RS] = xr[i];
#pragma unroll
            for (int i = 0; i < WLD; i++) Ws[cur ^ 1][lk][lr + i * RS] = wr[i];
        }
        if (t + 2 < NT) {
            // issue global loads for tile t+2 (land during compute)
#pragma unroll
            for (int i = 0; i < XLD; i++) xr[i] = Xp[i * RS * K + (t + 2) * BK];
#pragma unroll
            for (int i = 0; i < WLD; i++) wr[i] = Wp[i * RS * K + (t + 2) * BK];
        }

#pragma unroll
        for (int kk = 0; kk < BK; kk++) {
            float a[TM], b[TN];
            if (TM == 2) {
                float2 av = *reinterpret_cast<const float2*>(&Xs[cur][kk][ty * TM]);
                a[0] = av.x; a[1] = av.y;
            }
            if (TN == 4) {
                float4 bv = *reinterpret_cast<const float4*>(&Ws[cur][kk][tx * TN]);
                b[0] = bv.x; b[1] = bv.y; b[2] = bv.z; b[3] = bv.w;
            } else {
                float2 bv = *reinterpret_cast<const float2*>(&Ws[cur][kk][tx * TN]);
                b[0] = bv.x; b[1] = bv.y;
            }
#pragma unroll
            for (int i = 0; i < TM; i++)
#pragma unroll
                for (int j = 0; j < TN; j++)
                    acc[i][j] = __fmaf_rn(a[i], b[j], acc[i][j]);
        }

        if ((t & (CH - 1)) == (CH - 1)) {
            // fold chunk (left-associative), reset chunk accumulator
#pragma unroll
            for (int i = 0; i < TM; i++)
#pragma unroll
                for (int j = 0; j < TN; j++) {
                    tot[i][j] = __fadd_rn(tot[i][j], acc[i][j]);
                    acc[i][j] = 0.0f;
                }
        }
        __syncthreads();
    }

    // epilogue
#pragma unroll
    for (int i = 0; i < TM; i++) {
        int m = m0 + ty * TM + i;
#pragma unroll
        for (int j = 0; j < TN; j++) {
            int n = n0 + tx * TN + j;
            size_t idx = (size_t)m * N + n;
            if (EPI == 2) {
                out[idx] = tot[i][j];
            } else {
                float decay = __fmul_rn(__fmul_rn(VDECAY, v[idx]), __fadd_rn(1.0f, -s[idx]));
                float vv = __fadd_rn(__fadd_rn(decay, tot[i][j]), bias[n]);
                float ss = (vv > VTH) ? 1.0f : 0.0f;
                v[idx] = vv;
                s[idx] = ss;
                if (EPI == 1) out[idx] += ss;
            }
        }
    }
}

// ---------------- launcher ----------------
extern "C" void kernel_launch(void* const* d_in, const int* in_sizes, int n_in,
                              void* d_out, int out_size) {
    (void)in_sizes; (void)n_in; (void)out_size;
    const float* sd  = (const float*)d_in[0];
    const float* h0v = (const float*)d_in[1];
    const float* h0s = (const float*)d_in[2];
    const float* h1v = (const float*)d_in[3];
    const float* h1s = (const float*)d_in[4];
    const float* ov  = (const float*)d_in[5];
    const float* os  = (const float*)d_in[6];
    const float* W0  = (const float*)d_in[7];
    const float* b0  = (const float*)d_in[8];
    const float* W1  = (const float*)d_in[9];
    const float* b1  = (const float*)d_in[10];
    const float* Wo  = (const float*)d_in[11];
    const float* bo  = (const float*)d_in[12];
    float* out = (float*)d_out;

    float *xt, *gg0, *s0all, *v1, *s1, *vo, *so;
    cudaGetSymbolAddress((void**)&xt,    g_xt);
    cudaGetSymbolAddress((void**)&gg0,   g_g0);
    cudaGetSymbolAddress((void**)&s0all, g_s0all);
    cudaGetSymbolAddress((void**)&v1,    g_v1);
    cudaGetSymbolAddress((void**)&s1,    g_s1);
    cudaGetSymbolAddress((void**)&vo,    g_vo);
    cudaGetSymbolAddress((void**)&so,    g_so);

    setup_kernel<<<512, 256>>>(h1v, h1s, ov, os, out);

    dim3 tb(32, 8);
    dim3 tg(IN_DIM / 32, BATCH);
    transpose_kernel<<<tg, tb>>>(sd);

    // Layer0 batched over all timesteps: M = T*B = 4096 rows, full-chip GEMM.
    {
        dim3 grid(HID / 64, (TSTEPS * BATCH) / 32);   // (32, 128) = 4096 CTAs
        lif_gemm_kernel<HID, IN_DIM, 32, 64, 2, 4, 256, 2><<<grid, 256>>>(
            xt, W0, nullptr, nullptr, nullptr, gg0);
    }

    // Layer0 LIF recurrence (elementwise scan over T)
    lif0_scan_kernel<<<(BATCH * HID + 255) / 256, 256>>>(h0v, h0s, b0);

    dim3 grid1(HID / 64, BATCH / 32);      // (32, 4) = 128 CTAs
    dim3 gridO(OUT_DIM / 16, BATCH / 32);  // (32, 4) = 128 CTAs

    for (int t = 0; t < TSTEPS; t++) {
        lif_gemm_kernel<HID, HID, 32, 64, 2, 4, 256, 0><<<grid1, 256>>>(
            s0all + (size_t)t * BATCH * HID, W1, b1, v1, s1, nullptr);
        lif_gemm_kernel<OUT_DIM, HID, 32, 16, 2, 2, 128, 1><<<gridO, 128>>>(
            s1, Wo, bo, vo, so, out);
    }
}

// round 5
// speedup vs baseline: 3.0987x; 1.7376x over previous
#include <cuda_runtime.h>

// Problem constants (fixed by the dataset)
#define BATCH   128
#define IN_DIM  2048
#define HID     2048
#define OUT_DIM 512
#define TSTEPS  32
#define VDECAY  0.5f
#define VTH     0.5f
#define KCHUNK  512   // reference split-K chunk (bit-exact contract from R2)

// ---------------- device scratch (no allocations allowed) ----------------
__device__ float g_xt[TSTEPS * BATCH * IN_DIM];     // [T*B, K] transposed input
__device__ float g_g0[TSTEPS * BATCH * HID];        // layer0 raw GEMM results [T*B, H]
__device__ float g_s0all[TSTEPS * BATCH * HID];     // layer0 spikes per t [T*B, H]
__device__ float g_v1[BATCH * HID];
__device__ float g_s1[BATCH * HID];
__device__ float g_vo[BATCH * OUT_DIM];
__device__ float g_so[BATCH * OUT_DIM];
__device__ float g_p1[4 * BATCH * HID];             // GEMM1 split-K partials
__device__ float g_po[4 * BATCH * OUT_DIM];         // GEMMo split-K partials

// ---------------- setup: copy initial state, zero output ----------------
__global__ void setup_kernel(const float* __restrict__ h1v, const float* __restrict__ h1s,
                             const float* __restrict__ ov,  const float* __restrict__ os,
                             float* __restrict__ out) {
    int i = blockIdx.x * blockDim.x + threadIdx.x;
    int stride = gridDim.x * blockDim.x;
    for (int idx = i; idx < BATCH * HID; idx += stride) {
        g_v1[idx] = h1v[idx];
        g_s1[idx] = h1s[idx];
    }
    for (int idx = i; idx < BATCH * OUT_DIM; idx += stride) {
        g_vo[idx] = ov[idx];
        g_so[idx] = os[idx];
        out[idx]  = 0.0f;
    }
}

// ---------------- transpose spike_data [B, K, T] -> [T, B, K] ----------------
__global__ void transpose_kernel(const float* __restrict__ sd) {
    __shared__ float tile[32][33];
    int b  = blockIdx.y;
    int k0 = blockIdx.x * 32;
    int tx = threadIdx.x;  // 0..31
    int ty = threadIdx.y;  // 0..7
#pragma unroll
    for (int i = 0; i < 4; i++) {
        int kl = ty + i * 8;
        tile[kl][tx] = sd[(b * IN_DIM + k0 + kl) * TSTEPS + tx];
    }
    __syncthreads();
#pragma unroll
    for (int i = 0; i < 4; i++) {
        int t = ty + i * 8;
        g_xt[(t * BATCH + b) * IN_DIM + k0 + tx] = tile[tx][t];
    }
}

// ---------------- layer0 LIF scan over time (elementwise) ----------------
__global__ void lif0_scan_kernel(const float* __restrict__ h0v, const float* __restrict__ h0s,
                                 const float* __restrict__ b0) {
    int idx = blockIdx.x * blockDim.x + threadIdx.x;
    if (idx >= BATCH * HID) return;
    int h = idx % HID;
    float vv = h0v[idx];
    float ss = h0s[idx];
    float bb = b0[h];
#pragma unroll
    for (int t = 0; t < TSTEPS; t++) {
        float g = g_g0[t * BATCH * HID + idx];
        float decay = __fmul_rn(__fmul_rn(VDECAY, vv), __fadd_rn(1.0f, -ss));
        vv = __fadd_rn(__fadd_rn(decay, g), bb);
        ss = (vv > VTH) ? 1.0f : 0.0f;
        g_s0all[t * BATCH * HID + idx] = ss;
    }
}

// ---------------- fold split-K partials + LIF update ----------------
// tot = (((0+p0)+p1)+p2)+p3 left-assoc, exactly matching the in-kernel fold.
template <int N, bool ACC>
__global__ void fold_lif_kernel(const float* __restrict__ partial,
                                const float* __restrict__ bias,
                                float* __restrict__ v, float* __restrict__ s,
                                float* __restrict__ out, int MN) {
    int i = blockIdx.x * blockDim.x + threadIdx.x;
    if (i >= MN) return;
    float tot = 0.0f;
    tot = __fadd_rn(tot, partial[i]);
    tot = __fadd_rn(tot, partial[MN + i]);
    tot = __fadd_rn(tot, partial[2 * MN + i]);
    tot = __fadd_rn(tot, partial[3 * MN + i]);
    int n = i % N;
    float decay = __fmul_rn(__fmul_rn(VDECAY, v[i]), __fadd_rn(1.0f, -s[i]));
    float vv = __fadd_rn(__fadd_rn(decay, tot), bias[n]);
    float ss = (vv > VTH) ? 1.0f : 0.0f;
    v[i] = vv;
    s[i] = ss;
    if (ACC) out[i] += ss;
}

// ---------------- double-buffered GEMM tile kernel ----------------
// Per-element rounding contract: serial in-order FFMA within each 512-chunk,
// chunks folded left-associatively. If SPLITK: this CTA computes chunk
// blockIdx.z only and stores the raw chunk sum to out[z*M*N + m*N + n].
// Else: full K with in-kernel chunk folding; EPI==2 stores raw sum.
template <int M, int N, int KTOT, int BM, int BN, int TM, int TN, int THREADS,
          bool SPLITK, int EPI>
__global__ __launch_bounds__(THREADS) void gemm_kernel(
    const float* __restrict__ X,
    const float* __restrict__ W,
    float* __restrict__ out)
{
    constexpr int BK  = 16;
    constexpr int KLOC = SPLITK ? KCHUNK : KTOT;
    constexpr int NT  = KLOC / BK;         // tiles processed by this CTA
    constexpr int CH  = KCHUNK / BK;       // tiles per rounding chunk (32)
    constexpr int XP  = 4;                 // pad keeps float4 alignment (BM+4=36)
    constexpr int WP  = 4;                 // BN+4=68
    constexpr int XLD = BM * BK / THREADS;
    constexpr int WLD = BN * BK / THREADS;
    constexpr int RS  = THREADS / BK;

    __shared__ __align__(16) float Xs[2][BK][BM + XP];
    __shared__ __align__(16) float Ws[2][BK][BN + WP];

    const int tid = threadIdx.x;
    const int m0 = blockIdx.y * BM;
    const int n0 = blockIdx.x * BN;
    const int kbase = SPLITK ? blockIdx.z * KCHUNK : 0;

    const int lk = tid % BK;
    const int lr = tid / BK;
    const float* Xp = X + (size_t)(m0 + lr) * KTOT + kbase + lk;
    const float* Wp = W + (size_t)(n0 + lr) * KTOT + kbase + lk;

    const int tx = tid % (BN / TN);
    const int ty = tid / (BN / TN);

    float xr[XLD], wr[WLD];
    float acc[TM][TN], tot[TM][TN];
#pragma unroll
    for (int i = 0; i < TM; i++)
#pragma unroll
        for (int j = 0; j < TN; j++) { acc[i][j] = 0.0f; tot[i][j] = 0.0f; }

    // prologue: tile0 -> regs -> buf0 ; tile1 -> regs (in flight)
#pragma unroll
    for (int i = 0; i < XLD; i++) xr[i] = Xp[(size_t)i * RS * KTOT];
#pragma unroll
    for (int i = 0; i < WLD; i++) wr[i] = Wp[(size_t)i * RS * KTOT];
#pragma unroll
    for (int i = 0; i < XLD; i++) Xs[0][lk][lr + i * RS] = xr[i];
#pragma unroll
    for (int i = 0; i < WLD; i++) Ws[0][lk][lr + i * RS] = wr[i];
#pragma unroll
    for (int i = 0; i < XLD; i++) xr[i] = Xp[(size_t)i * RS * KTOT + BK];
#pragma unroll
    for (int i = 0; i < WLD; i++) wr[i] = Wp[(size_t)i * RS * KTOT + BK];
    __syncthreads();

    for (int t = 0; t < NT; t++) {
        const int cur = t & 1;
        if (t + 1 < NT) {
#pragma unroll
            for (int i = 0; i < XLD; i++) Xs[cur ^ 1][lk][lr + i * RS] = xr[i];
#pragma unroll
            for (int i = 0; i < WLD; i++) Ws[cur ^ 1][lk][lr + i * RS] = wr[i];
        }
        if (t + 2 < NT) {
#pragma unroll
            for (int i = 0; i < XLD; i++) xr[i] = Xp[(size_t)i * RS * KTOT + (t + 2) * BK];
#pragma unroll
            for (int i = 0; i < WLD; i++) wr[i] = Wp[(size_t)i * RS * KTOT + (t + 2) * BK];
        }

#pragma unroll
        for (int kk = 0; kk < BK; kk++) {
            float a[TM], b[TN];
            float4 av = *reinterpret_cast<const float4*>(&Xs[cur][kk][ty * TM]);
            a[0] = av.x; a[1] = av.y; a[2] = av.z; a[3] = av.w;
            float4 bv = *reinterpret_cast<const float4*>(&Ws[cur][kk][tx * TN]);
            b[0] = bv.x; b[1] = bv.y; b[2] = bv.z; b[3] = bv.w;
#pragma unroll
            for (int i = 0; i < TM; i++)
#pragma unroll
                for (int j = 0; j < TN; j++)
                    acc[i][j] = __fmaf_rn(a[i], b[j], acc[i][j]);
        }

        if ((t & (CH - 1)) == (CH - 1)) {
#pragma unroll
            for (int i = 0; i < TM; i++)
#pragma unroll
                for (int j = 0; j < TN; j++) {
                    tot[i][j] = __fadd_rn(tot[i][j], acc[i][j]);
                    acc[i][j] = 0.0f;
                }
        }
        __syncthreads();
    }

    // epilogue: store raw sums (partials if SPLITK, full fold result otherwise)
    const size_t zoff = SPLITK ? (size_t)blockIdx.z * M * N : 0;
#pragma unroll
    for (int i = 0; i < TM; i++) {
        int m = m0 + ty * TM + i;
#pragma unroll
        for (int j = 0; j < TN; j++) {
            int n = n0 + tx * TN + j;
            out[zoff + (size_t)m * N + n] = tot[i][j];
        }
    }
    (void)EPI;
}

// ---------------- launcher ----------------
extern "C" void kernel_launch(void* const* d_in, const int* in_sizes, int n_in,
                              void* d_out, int out_size) {
    (void)in_sizes; (void)n_in; (void)out_size;
    const float* sd  = (const float*)d_in[0];
    const float* h0v = (const float*)d_in[1];
    const float* h0s = (const float*)d_in[2];
    const float* h1v = (const float*)d_in[3];
    const float* h1s = (const float*)d_in[4];
    const float* ov  = (const float*)d_in[5];
    const float* os  = (const float*)d_in[6];
    const float* W0  = (const float*)d_in[7];
    const float* b0  = (const float*)d_in[8];
    const float* W1  = (const float*)d_in[9];
    const float* b1  = (const float*)d_in[10];
    const float* Wo  = (const float*)d_in[11];
    const float* bo  = (const float*)d_in[12];
    float* out = (float*)d_out;

    float *xt, *gg0, *s0all, *v1, *s1, *vo, *so, *p1, *po;
    cudaGetSymbolAddress((void**)&xt,    g_xt);
    cudaGetSymbolAddress((void**)&gg0,   g_g0);
    cudaGetSymbolAddress((void**)&s0all, g_s0all);
    cudaGetSymbolAddress((void**)&v1,    g_v1);
    cudaGetSymbolAddress((void**)&s1,    g_s1);
    cudaGetSymbolAddress((void**)&vo,    g_vo);
    cudaGetSymbolAddress((void**)&so,    g_so);
    cudaGetSymbolAddress((void**)&p1,    g_p1);
    cudaGetSymbolAddress((void**)&po,    g_po);

    setup_kernel<<<512, 256>>>(h1v, h1s, ov, os, out);

    dim3 tb(32, 8);
    dim3 tg(IN_DIM / 32, BATCH);
    transpose_kernel<<<tg, tb>>>(sd);

    // Layer0 batched over all timesteps: M = T*B = 4096, full K in-kernel fold.
    {
        dim3 grid(HID / 64, (TSTEPS * BATCH) / 32);   // 4096 CTAs
        gemm_kernel<TSTEPS * BATCH, HID, IN_DIM, 32, 64, 4, 4, 128, false, 2>
            <<<grid, 128>>>(xt, W0, gg0);
    }

    // Layer0 LIF recurrence (elementwise scan over T)
    lif0_scan_kernel<<<(BATCH * HID + 255) / 256, 256>>>(h0v, h0s, b0);

    dim3 grid1(HID / 64, BATCH / 32, 4);      // (32,4,4) = 512 CTAs
    dim3 gridO(OUT_DIM / 64, BATCH / 32, 4);  // (8,4,4)  = 128 CTAs

    const int MN1 = BATCH * HID;      // 262144
    const int MNo = BATCH * OUT_DIM;  // 65536

    for (int t = 0; t < TSTEPS; t++) {
        gemm_kernel<BATCH, HID, HID, 32, 64, 4, 4, 128, true, 2><<<grid1, 128>>>(
            s0all + (size_t)t * BATCH * HID, W1, p1);
        fold_lif_kernel<HID, false><<<(MN1 + 255) / 256, 256>>>(
            p1, b1, v1, s1, nullptr, MN1);
        gemm_kernel<BATCH, OUT_DIM, HID, 32, 64, 4, 4, 128, true, 2><<<gridO, 128>>>(
            s1, Wo, po);
        fold_lif_kernel<OUT_DIM, true><<<(MNo + 255) / 256, 256>>>(
            po, bo, vo, so, out, MNo);
    }
}